// round 13
// baseline (speedup 1.0000x reference)
#include <cuda_runtime.h>
#include <cstdint>

#define CIN   128
#define CHID  256
#define COUT  128
#define HW    1600
#define TP    128
#define NT    256
#define NTILE 13

#define SXS 136    // x/h row stride (mod 32 == 8 -> conflict-free paired LDS.64)

// SMEM float offsets
#define OXS 0                        // x [128 c][136], columns pair-permuted
#define OH0 17408                    // h buf0 [64 ch][136], pair-permuted
#define OH1 26112                    // h buf1
#define OGB 34816                    // gated b2 [128]
#define SMB ((34816 + 128) * 4)      // 139776 B -> 1 CTA/SM

// weights packed in per-warp fragment order, tf32-rounded (1MB each)
__device__ float2 sW1p[131072];
__device__ float2 sW2p[131072];
__device__ int    g_idx[256];

__device__ __forceinline__ float tf32f(float v) {
    uint32_t r;
    asm("cvt.rna.tf32.f32 %0, %1;" : "=r"(r) : "f"(v));
    return __uint_as_float(r);
}
__device__ __forceinline__ void mma8(float (&d)[4], const float (&a)[4], float b0, float b1) {
    asm("mma.sync.aligned.m16n8k8.row.col.f32.tf32.tf32.f32 "
        "{%0,%1,%2,%3}, {%4,%5,%6,%7}, {%8,%9}, {%0,%1,%2,%3};"
        : "+f"(d[0]), "+f"(d[1]), "+f"(d[2]), "+f"(d[3])
        : "r"(__float_as_uint(a[0])), "r"(__float_as_uint(a[1])),
          "r"(__float_as_uint(a[2])), "r"(__float_as_uint(a[3])),
          "r"(__float_as_uint(b0)),  "r"(__float_as_uint(b1)));
}

__global__ void prep_idx(const int* __restrict__ raw) {
    __shared__ int odd_nz;
    if (threadIdx.x == 0) odd_nz = 0;
    __syncthreads();
    if (threadIdx.x < 128) {
        if (raw[2 * threadIdx.x + 1] != 0) atomicAdd(&odd_nz, 1);
    }
    __syncthreads();
    bool is64 = (odd_nz == 0);
    g_idx[threadIdx.x] = is64 ? raw[2 * threadIdx.x] : raw[threadIdx.x];
}

// Pack weights into per-warp fragment order (layout identical to R8-R12).
__global__ void prep_w(const float* __restrict__ W1, const float* __restrict__ W2) {
    int tid = blockIdx.x * blockDim.x + threadIdx.x;   // 0..131071
    int lane = tid & 31, g = lane >> 2, t = lane & 3;
    {
        int half = (tid >> 5) & 1, k = (tid >> 6) & 15, wm = (tid >> 10) & 3;
        int j = (tid >> 12) & 3,  e = (tid >> 14) & 7;
        int ch = j * 64 + wm * 16 + half * 8 + g;
        int c  = 8 * k + t;
        const float* s = W1 + (size_t)e * 32768 + (size_t)ch * 128;
        sW1p[tid] = make_float2(tf32f(s[c]), tf32f(s[c + 4]));
    }
    {
        int half = (tid >> 5) & 1, k = (tid >> 6) & 7, mb = (tid >> 9) & 7;
        int j = (tid >> 12) & 3,  e = (tid >> 14) & 7;
        int oc = mb * 16 + half * 8 + g;
        int ch = j * 64 + 8 * k + t;
        const float* s = W2 + (size_t)e * 32768 + (size_t)oc * 256;
        sW2p[tid] = make_float2(tf32f(s[ch]), tf32f(s[ch + 4]));
    }
}

__global__ __launch_bounds__(NT, 1)
void moe_tf32(const float* __restrict__ x,
              const float* __restrict__ gate_w,
              const float* __restrict__ b1,
              const float* __restrict__ b2,
              float* __restrict__ out)
{
    extern __shared__ float sm[];
    const int tid  = threadIdx.x;
    const int lane = tid & 31;
    const int warp = tid >> 5;
    const int g    = lane >> 2;
    const int t    = lane & 3;
    const int wm1  = warp >> 2;        // G1: 0-1 (32 ch each)
    const int wn1  = warp & 3;         // G1: 0-3 (32 px each)
    const int wm2  = warp >> 1;        // G2: 0-3 (32 oc each)
    const int wn2  = warp & 1;         // G2: 0-1 (64 px each)
    const int b    = blockIdx.y;
    const int p0   = blockIdx.x * TP;

    const int   e0 = g_idx[b * 2],           e1 = g_idx[b * 2 + 1];
    const float g0 = __ldg(&gate_w[b * 2]);
    const float g1 = __ldg(&gate_w[b * 2 + 1]);

    if (tid < 128)
        sm[OGB + tid] = g0 * __ldg(&b2[e0 * COUT + tid]) + g1 * __ldg(&b2[e1 * COUT + tid]);

    float2 g1r[2][4];   // G1 A-fragment ring: [stage][a0lo,a0hi,a1lo,a1hi]
    float2 g2r[2][4];   // G2 A-fragment ring

    // ---- prologue preload: GEMM1(it=0) fragments k=0,1 for both m-tiles ----
    {
        const float2* pa = sW1p + (size_t)((e0 * 4 + 0) * 4 + wm1 * 2) * 1024 + lane;
        g1r[0][0] = __ldg(pa);        g1r[0][1] = __ldg(pa + 32);
        g1r[0][2] = __ldg(pa + 1024); g1r[0][3] = __ldg(pa + 1056);
        g1r[1][0] = __ldg(pa + 64);   g1r[1][1] = __ldg(pa + 96);
        g1r[1][2] = __ldg(pa + 1088); g1r[1][3] = __ldg(pa + 1120);
    }

    // ---- stage x pair-permuted + tf32-rounded (8 blocks of 16 px) ----
    {
        const float* xb = x + (size_t)b * CIN * HW + p0;
        #pragma unroll
        for (int i = 0; i < 8; i++) {
            int u = tid + i * NT;
            int c = u >> 4, blk = (u >> 1) & 7, h4 = u & 1;
            float4 lo, hi;
            if (p0 + blk * 16 < HW) {
                const float* src = xb + (size_t)c * HW + blk * 16 + h4 * 4;
                lo = *(const float4*)(src);
                hi = *(const float4*)(src + 8);
            } else {
                lo = hi = make_float4(0.f, 0.f, 0.f, 0.f);
            }
            float* dst = sm + OXS + c * SXS + blk * 16 + h4 * 8;
            *(float2*)(dst + 0) = make_float2(tf32f(lo.x), tf32f(hi.x));
            *(float2*)(dst + 2) = make_float2(tf32f(lo.y), tf32f(hi.y));
            *(float2*)(dst + 4) = make_float2(tf32f(lo.z), tf32f(hi.z));
            *(float2*)(dst + 6) = make_float2(tf32f(lo.w), tf32f(hi.w));
        }
    }
    __syncthreads();

    float acc2[2][8][4];
    #pragma unroll
    for (int m = 0; m < 2; m++)
        #pragma unroll
        for (int n = 0; n < 8; n++)
            #pragma unroll
            for (int q = 0; q < 4; q++) acc2[m][n][q] = 0.f;

    #pragma unroll 1
    for (int it = 0; it < 8; it++) {
        const int   e    = (it < 4) ? e0 : e1;
        const int   j    = it & 3;
        const float gate = (it < 4) ? g0 : g1;

        // ---- GEMM1(it): 32ch x 32px per warp (2 m-tiles x 4 n-tiles) ----
        float acc1[2][4][4];
        #pragma unroll
        for (int m = 0; m < 2; m++)
            #pragma unroll
            for (int n = 0; n < 4; n++)
                #pragma unroll
                for (int q = 0; q < 4; q++) acc1[m][n][q] = 0.f;
        {
            const float2* pa = sW1p + (size_t)((e * 4 + j) * 4 + wm1 * 2) * 1024 + lane;
            #pragma unroll
            for (int k = 0; k < 16; k++) {
                const int s = k & 1;
                float a0[4] = {g1r[s][0].x, g1r[s][1].x, g1r[s][0].y, g1r[s][1].y};
                float a1[4] = {g1r[s][2].x, g1r[s][3].x, g1r[s][2].y, g1r[s][3].y};
                if (k < 14) {
                    g1r[s][0] = __ldg(pa + (k + 2) * 64);
                    g1r[s][1] = __ldg(pa + (k + 2) * 64 + 32);
                    g1r[s][2] = __ldg(pa + 1024 + (k + 2) * 64);
                    g1r[s][3] = __ldg(pa + 1024 + (k + 2) * 64 + 32);
                }
                const float* base = sm + OXS + (8 * k + t) * SXS + wn1 * 32;
                float2 p00 = *(const float2*)(base + 2 * g);
                float2 p10 = *(const float2*)(base + 4 * SXS + 2 * g);
                float2 p01 = *(const float2*)(base + 16 + 2 * g);
                float2 p11 = *(const float2*)(base + 16 + 4 * SXS + 2 * g);
                mma8(acc1[0][0], a0, p00.x, p10.x);
                mma8(acc1[0][1], a0, p00.y, p10.y);
                mma8(acc1[0][2], a0, p01.x, p11.x);
                mma8(acc1[0][3], a0, p01.y, p11.y);
                mma8(acc1[1][0], a1, p00.x, p10.x);
                mma8(acc1[1][1], a1, p00.y, p10.y);
                mma8(acc1[1][2], a1, p01.x, p11.x);
                mma8(acc1[1][3], a1, p01.y, p11.y);
            }
        }

        // ---- GEMM2(it-1): 32oc x 64px per warp (2 m-tiles x 8 n-tiles) ----
        if (it > 0) {
            const int ep = (it - 1 < 4) ? e0 : e1;
            const int jp = (it - 1) & 3;
            const float* hb = sm + (((it - 1) & 1) ? OH1 : OH0);
            const float2* pb = sW2p + (size_t)((ep * 4 + jp) * 8 + wm2 * 2) * 512 + lane;
            #pragma unroll
            for (int k = 0; k < 8; k++) {
                const int s = k & 1;
                float a0[4] = {g2r[s][0].x, g2r[s][1].x, g2r[s][0].y, g2r[s][1].y};
                float a1[4] = {g2r[s][2].x, g2r[s][3].x, g2r[s][2].y, g2r[s][3].y};
                if (k < 6) {
                    g2r[s][0] = __ldg(pb + (k + 2) * 64);
                    g2r[s][1] = __ldg(pb + (k + 2) * 64 + 32);
                    g2r[s][2] = __ldg(pb + 512 + (k + 2) * 64);
                    g2r[s][3] = __ldg(pb + 512 + (k + 2) * 64 + 32);
                }
                const float* rb = hb + (8 * k + t) * SXS + wn2 * 64;
                #pragma unroll
                for (int blk = 0; blk < 4; blk++) {
                    float2 u0 = *(const float2*)(rb + blk * 16 + 2 * g);
                    float2 u1 = *(const float2*)(rb + blk * 16 + 4 * SXS + 2 * g);
                    mma8(acc2[0][2 * blk],     a0, u0.x, u1.x);
                    mma8(acc2[0][2 * blk + 1], a0, u0.y, u1.y);
                    mma8(acc2[1][2 * blk],     a1, u0.x, u1.x);
                    mma8(acc2[1][2 * blk + 1], a1, u0.y, u1.y);
                }
            }
        }

        // ---- epilogue: bias + SiLU + gate -> h[it&1] (pair-permuted) ----
        {
            float* hb = sm + ((it & 1) ? OH1 : OH0);
            #pragma unroll
            for (int mi = 0; mi < 2; mi++) {
                const float bia0 = __ldg(b1 + e * CHID + j * 64 + wm1 * 32 + mi * 16 + g);
                const float bia1 = __ldg(b1 + e * CHID + j * 64 + wm1 * 32 + mi * 16 + 8 + g);
                int ch = wm1 * 32 + mi * 16 + g;
                #pragma unroll
                for (int ni = 0; ni < 4; ni++) {
                    int loc = wn1 * 32 + (ni >> 1) * 16 + 4 * t + (ni & 1);
                    float v0 = acc1[mi][ni][0] + bia0;
                    float v1 = acc1[mi][ni][1] + bia0;
                    float v2 = acc1[mi][ni][2] + bia1;
                    float v3 = acc1[mi][ni][3] + bia1;
                    float h0 = gate * (v0 / (1.f + __expf(-v0)));
                    float h1 = gate * (v1 / (1.f + __expf(-v1)));
                    float h2 = gate * (v2 / (1.f + __expf(-v2)));
                    float h3 = gate * (v3 / (1.f + __expf(-v3)));
                    hb[ch * SXS + loc]           = tf32f(h0);
                    hb[ch * SXS + loc + 2]       = tf32f(h1);
                    hb[(ch + 8) * SXS + loc]     = tf32f(h2);
                    hb[(ch + 8) * SXS + loc + 2] = tf32f(h3);
                }
            }

            // preload GEMM1(it+1) fragments k=0,1 (ride out the barrier)
            if (it < 7) {
                const int en = (it + 1 < 4) ? e0 : e1;
                const int jn = (it + 1) & 3;
                const float2* pan = sW1p + (size_t)((en * 4 + jn) * 4 + wm1 * 2) * 1024 + lane;
                g1r[0][0] = __ldg(pan);        g1r[0][1] = __ldg(pan + 32);
                g1r[0][2] = __ldg(pan + 1024); g1r[0][3] = __ldg(pan + 1056);
                g1r[1][0] = __ldg(pan + 64);   g1r[1][1] = __ldg(pan + 96);
                g1r[1][2] = __ldg(pan + 1088); g1r[1][3] = __ldg(pan + 1120);
            }
            // preload GEMM2(it) fragments k=0,1 (consumed next iter / tail)
            {
                const float2* pc = sW2p + (size_t)((e * 4 + j) * 8 + wm2 * 2) * 512 + lane;
                g2r[0][0] = __ldg(pc);       g2r[0][1] = __ldg(pc + 32);
                g2r[0][2] = __ldg(pc + 512); g2r[0][3] = __ldg(pc + 544);
                g2r[1][0] = __ldg(pc + 64);  g2r[1][1] = __ldg(pc + 96);
                g2r[1][2] = __ldg(pc + 576); g2r[1][3] = __ldg(pc + 608);
            }
        }
        __syncthreads();   // publish h(it); GEMM2(it-1) complete CTA-wide
    }

    // ---- tail: GEMM2(7) ----
    {
        const float* hb = sm + OH1;
        const float2* pb = sW2p + (size_t)((e1 * 4 + 3) * 8 + wm2 * 2) * 512 + lane;
        #pragma unroll
        for (int k = 0; k < 8; k++) {
            const int s = k & 1;
            float a0[4] = {g2r[s][0].x, g2r[s][1].x, g2r[s][0].y, g2r[s][1].y};
            float a1[4] = {g2r[s][2].x, g2r[s][3].x, g2r[s][2].y, g2r[s][3].y};
            if (k < 6) {
                g2r[s][0] = __ldg(pb + (k + 2) * 64);
                g2r[s][1] = __ldg(pb + (k + 2) * 64 + 32);
                g2r[s][2] = __ldg(pb + 512 + (k + 2) * 64);
                g2r[s][3] = __ldg(pb + 512 + (k + 2) * 64 + 32);
            }
            const float* rb = hb + (8 * k + t) * SXS + wn2 * 64;
            #pragma unroll
            for (int blk = 0; blk < 4; blk++) {
                float2 u0 = *(const float2*)(rb + blk * 16 + 2 * g);
                float2 u1 = *(const float2*)(rb + blk * 16 + 4 * SXS + 2 * g);
                mma8(acc2[0][2 * blk],     a0, u0.x, u1.x);
                mma8(acc2[0][2 * blk + 1], a0, u0.y, u1.y);
                mma8(acc2[1][2 * blk],     a1, u0.x, u1.x);
                mma8(acc2[1][2 * blk + 1], a1, u0.y, u1.y);
            }
        }
    }

    // ---- final store: acc2 + gated b2 -> out ----
    {
        float* ob = out + (size_t)b * COUT * HW;
        #pragma unroll
        for (int mi = 0; mi < 2; mi++) {
            int oc = wm2 * 32 + 16 * mi + g;
            float gba = sm[OGB + oc], gbb = sm[OGB + oc + 8];
            #pragma unroll
            for (int ni = 0; ni < 8; ni++) {
                int pxb = p0 + wn2 * 64 + ni * 8;
                if (pxb < HW) {
                    int px = pxb + 2 * t;
                    *(float2*)(ob + (size_t)oc * HW + px) =
                        make_float2(acc2[mi][ni][0] + gba, acc2[mi][ni][1] + gba);
                    *(float2*)(ob + (size_t)(oc + 8) * HW + px) =
                        make_float2(acc2[mi][ni][2] + gbb, acc2[mi][ni][3] + gbb);
                }
            }
        }
    }
}

extern "C" void kernel_launch(void* const* d_in, const int* in_sizes, int n_in,
                              void* d_out, int out_size) {
    const float* x   = (const float*)d_in[0];
    const float* wts = (const float*)d_in[1];
    const int*   idx = (const int*)d_in[2];
    const float* W1  = (const float*)d_in[3];
    const float* b1  = (const float*)d_in[4];
    const float* W2  = (const float*)d_in[5];
    const float* b2  = (const float*)d_in[6];
    float* out = (float*)d_out;
    (void)in_sizes; (void)n_in; (void)out_size;

    prep_idx<<<1, 256>>>(idx);
    prep_w<<<256, 512>>>(W1, W2);

    cudaFuncSetAttribute(moe_tf32, cudaFuncAttributeMaxDynamicSharedMemorySize, SMB);
    dim3 grid(NTILE, 128);
    moe_tf32<<<grid, NT, SMB>>>(x, wts, b1, b2, out);
}

// round 14
// speedup vs baseline: 2.1569x; 2.1569x over previous
#include <cuda_runtime.h>
#include <cuda_fp16.h>
#include <cstdint>

#define CIN   128
#define CHID  256
#define COUT  128
#define HW    1600
#define TP    64
#define NT    256
#define NTILE 25

#define SXW 72     // x row stride in u32 words (mod 32 == 8 -> conflict-free LDS.64)
#define SHW 40     // h row stride in u32 words (mod 32 == 8)

// SMEM u32-word offsets
#define OXS 0                        // x  [64 kpair][72] u32 (fp16x2, px pair-permuted)
#define OHB 4608                     // h: 2 halves x 2 bufs x [32 kpair][40]
#define HBSZ 1280
#define OGB 9728                     // gated b2 [128] (float view)
#define SMB ((9728 + 128) * 4)       // 39424 B -> 2 CTAs/SM

// weights packed as fp16 MMA A-fragments (one uint4 per lane per k16-step), 512KB each
__device__ uint4 sW1h[32768];
__device__ uint4 sW2h[32768];
__device__ int   g_idx[256];

__device__ __forceinline__ uint32_t pkh(float a, float b) {
    __half2 h = __floats2half2_rn(a, b);   // low = a
    return *reinterpret_cast<uint32_t*>(&h);
}
__device__ __forceinline__ void mmah(float (&d)[4], const uint4& a, uint32_t b0, uint32_t b1) {
    asm("mma.sync.aligned.m16n8k16.row.col.f32.f16.f16.f32 "
        "{%0,%1,%2,%3}, {%4,%5,%6,%7}, {%8,%9}, {%0,%1,%2,%3};"
        : "+f"(d[0]), "+f"(d[1]), "+f"(d[2]), "+f"(d[3])
        : "r"(a.x), "r"(a.y), "r"(a.z), "r"(a.w), "r"(b0), "r"(b1));
}
#define HBAR(id) asm volatile("bar.sync %0, 128;" :: "r"(id) : "memory")

__global__ void prep_idx(const int* __restrict__ raw) {
    __shared__ int odd_nz;
    if (threadIdx.x == 0) odd_nz = 0;
    __syncthreads();
    if (threadIdx.x < 128) {
        if (raw[2 * threadIdx.x + 1] != 0) atomicAdd(&odd_nz, 1);
    }
    __syncthreads();
    bool is64 = (odd_nz == 0);
    g_idx[threadIdx.x] = is64 ? raw[2 * threadIdx.x] : raw[threadIdx.x];
}

// Pack weights into fp16 A-fragment order.
// sW1h idx: (((e*4+j)*4 + wm)*8 + ks)*32 + lane  -> uint4 {a0,a1,a2,a3}
// sW2h idx: (((e*4+j)*8 + mb)*4 + ks)*32 + lane, k-order PERMUTED so that
//   permuted col 2k (kpair k: blk=k>>3, gg=k&7) -> channel j*64 + 16*blk + gg, 2k+1 -> +8
__global__ void prep_wh(const float* __restrict__ W1, const float* __restrict__ W2) {
    int tid = blockIdx.x * blockDim.x + threadIdx.x;    // 0..32767
    int lane = tid & 31, g = lane >> 2, t = lane & 3;
    {
        int ks = (tid >> 5) & 7, wm = (tid >> 8) & 3, j = (tid >> 10) & 3, e = (tid >> 12) & 7;
        const float* s = W1 + (size_t)e * 32768;
        int ch = j * 64 + wm * 16 + g;
        int c0 = ks * 16 + 2 * t;
        uint4 v;
        v.x = pkh(s[ch * 128 + c0],           s[ch * 128 + c0 + 1]);
        v.y = pkh(s[(ch + 8) * 128 + c0],     s[(ch + 8) * 128 + c0 + 1]);
        v.z = pkh(s[ch * 128 + c0 + 8],       s[ch * 128 + c0 + 9]);
        v.w = pkh(s[(ch + 8) * 128 + c0 + 8], s[(ch + 8) * 128 + c0 + 9]);
        sW1h[tid] = v;
    }
    {
        int ks = (tid >> 5) & 3, mb = (tid >> 7) & 7, j = (tid >> 10) & 3, e = (tid >> 12) & 7;
        const float* s = W2 + (size_t)e * 32768;
        int oc = mb * 16 + g;
        int c0 = ks * 16 + 2 * t;
        auto chan = [&](int c) { int kp = c >> 1; return j * 64 + (kp >> 3) * 16 + (kp & 7) + (c & 1) * 8; };
        uint4 v;
        v.x = pkh(s[oc * 256 + chan(c0)],           s[oc * 256 + chan(c0 + 1)]);
        v.y = pkh(s[(oc + 8) * 256 + chan(c0)],     s[(oc + 8) * 256 + chan(c0 + 1)]);
        v.z = pkh(s[oc * 256 + chan(c0 + 8)],       s[oc * 256 + chan(c0 + 9)]);
        v.w = pkh(s[(oc + 8) * 256 + chan(c0 + 8)], s[(oc + 8) * 256 + chan(c0 + 9)]);
        sW2h[tid] = v;
    }
}

__global__ __launch_bounds__(NT, 2)
void moe_fp16(const float* __restrict__ x,
              const float* __restrict__ gate_w,
              const float* __restrict__ b1,
              const float* __restrict__ b2,
              float* __restrict__ out)
{
    extern __shared__ uint32_t smu[];
    float* smf = (float*)smu;
    const int tid  = threadIdx.x;
    const int lane = tid & 31;
    const int warp = tid >> 5;
    const int g    = lane >> 2;
    const int t    = lane & 3;
    const int hf   = warp >> 2;        // half: 0 -> px [0,32), 1 -> px [32,64)
    const int wm   = warp & 3;         // 16-ch block (G1) / 32-oc block (G2)
    const int b    = blockIdx.y;
    const int p0   = blockIdx.x * TP;

    const int   e0 = g_idx[b * 2],           e1 = g_idx[b * 2 + 1];
    const float g0 = __ldg(&gate_w[b * 2]);
    const float g1 = __ldg(&gate_w[b * 2 + 1]);

    if (tid < 128)
        smf[OGB + tid] = g0 * __ldg(&b2[e0 * COUT + tid]) + g1 * __ldg(&b2[e1 * COUT + tid]);

    // ---- stage x: channel pairs packed fp16x2, px pair-permuted within 16-blocks ----
    {
        const float* xb = x + (size_t)b * CIN * HW + p0;
        int kx = tid >> 2, blk = tid & 3;
        const float* r0 = xb + (size_t)(2 * kx) * HW + blk * 16;
        const float* r1 = r0 + HW;
        uint32_t w[16];
        #pragma unroll
        for (int q = 0; q < 4; q++) {
            float4 u0 = *(const float4*)(r0 + 4 * q);
            float4 u1 = *(const float4*)(r1 + 4 * q);
            w[4 * q + 0] = pkh(u0.x, u1.x);
            w[4 * q + 1] = pkh(u0.y, u1.y);
            w[4 * q + 2] = pkh(u0.z, u1.z);
            w[4 * q + 3] = pkh(u0.w, u1.w);
        }
        uint4* dst = (uint4*)(smu + OXS + kx * SXW + blk * 16);
        dst[0] = make_uint4(w[0], w[8],  w[1], w[9]);
        dst[1] = make_uint4(w[2], w[10], w[3], w[11]);
        dst[2] = make_uint4(w[4], w[12], w[5], w[13]);
        dst[3] = make_uint4(w[6], w[14], w[7], w[15]);
    }
    __syncthreads();

    uint32_t* const hbuf0 = smu + OHB + hf * 2 * HBSZ;
    uint32_t* const hbuf1 = hbuf0 + HBSZ;

    float acc2[2][4][4];
    #pragma unroll
    for (int m = 0; m < 2; m++)
        #pragma unroll
        for (int n = 0; n < 4; n++)
            #pragma unroll
            for (int q = 0; q < 4; q++) acc2[m][n][q] = 0.f;

    #pragma unroll 1
    for (int it = 0; it < 8; it++) {
        const int   e    = (it < 4) ? e0 : e1;
        const int   j    = it & 3;
        const float gate = (it < 4) ? g0 : g1;

        // ---- GEMM1(it): D1[16ch x 32px] per warp; 8 k16-steps ----
        float acc1[4][4];
        #pragma unroll
        for (int n = 0; n < 4; n++)
            #pragma unroll
            for (int q = 0; q < 4; q++) acc1[n][q] = 0.f;
        {
            const uint4* pa = sW1h + ((e * 4 + j) * 4 + wm) * 256 + lane;
            uint4 ac = __ldg(pa);
            #pragma unroll
            for (int ks = 0; ks < 8; ks++) {
                uint4 an;
                if (ks < 7) an = __ldg(pa + (ks + 1) * 32);
                const uint32_t* xr0 = smu + OXS + (8 * ks + t) * SXW + hf * 32;
                const uint32_t* xr1 = xr0 + 4 * SXW;
                uint2 b00 = *(const uint2*)(xr0 + 2 * g);
                uint2 b10 = *(const uint2*)(xr1 + 2 * g);
                uint2 b01 = *(const uint2*)(xr0 + 16 + 2 * g);
                uint2 b11 = *(const uint2*)(xr1 + 16 + 2 * g);
                mmah(acc1[0], ac, b00.x, b10.x);
                mmah(acc1[1], ac, b00.y, b10.y);
                mmah(acc1[2], ac, b01.x, b11.x);
                mmah(acc1[3], ac, b01.y, b11.y);
                ac = an;
            }
        }

        // ---- GEMM2(it-1): D2[32oc x 32px] per warp; 4 k16-steps, permuted k ----
        if (it > 0) {
            const int ep = (it - 1 < 4) ? e0 : e1;
            const int jp = (it - 1) & 3;
            const uint32_t* hb = ((it - 1) & 1) ? hbuf1 : hbuf0;
            const uint4* pb = sW2h + ((ep * 4 + jp) * 8 + wm * 2) * 128 + lane;
            uint4 a0c = __ldg(pb), a1c = __ldg(pb + 128);
            #pragma unroll
            for (int ks = 0; ks < 4; ks++) {
                uint4 a0n, a1n;
                if (ks < 3) { a0n = __ldg(pb + (ks + 1) * 32); a1n = __ldg(pb + 128 + (ks + 1) * 32); }
                const uint32_t* hr0 = hb + (8 * ks + t) * SHW;
                const uint32_t* hr1 = hr0 + 4 * SHW;
                uint2 q00 = *(const uint2*)(hr0 + 2 * g);
                uint2 q10 = *(const uint2*)(hr1 + 2 * g);
                uint2 q01 = *(const uint2*)(hr0 + 16 + 2 * g);
                uint2 q11 = *(const uint2*)(hr1 + 16 + 2 * g);
                mmah(acc2[0][0], a0c, q00.x, q10.x);
                mmah(acc2[0][1], a0c, q00.y, q10.y);
                mmah(acc2[0][2], a0c, q01.x, q11.x);
                mmah(acc2[0][3], a0c, q01.y, q11.y);
                mmah(acc2[1][0], a1c, q00.x, q10.x);
                mmah(acc2[1][1], a1c, q00.y, q10.y);
                mmah(acc2[1][2], a1c, q01.x, q11.x);
                mmah(acc2[1][3], a1c, q01.y, q11.y);
                a0c = a0n; a1c = a1n;
            }
        }

        // ---- epilogue: bias + SiLU + gate -> h[it&1], packed (g, g+8) channel pairs ----
        {
            const float bia0 = __ldg(b1 + e * CHID + j * 64 + wm * 16 + g);
            const float bia1 = __ldg(b1 + e * CHID + j * 64 + wm * 16 + 8 + g);
            uint32_t* hb = (it & 1) ? hbuf1 : hbuf0;
            uint32_t* hrow = hb + (8 * wm + g) * SHW;
            #pragma unroll
            for (int ni = 0; ni < 4; ni++) {
                int loc = (ni >> 1) * 16 + 4 * t + (ni & 1);
                float v0 = acc1[ni][0] + bia0;   // row g,  col 8ni+2t
                float v1 = acc1[ni][1] + bia0;   // row g,  col 8ni+2t+1
                float v2 = acc1[ni][2] + bia1;   // row g+8, col 8ni+2t
                float v3 = acc1[ni][3] + bia1;
                float h0 = gate * (v0 / (1.f + __expf(-v0)));
                float h1 = gate * (v1 / (1.f + __expf(-v1)));
                float h2 = gate * (v2 / (1.f + __expf(-v2)));
                float h3 = gate * (v3 / (1.f + __expf(-v3)));
                hrow[loc]     = pkh(h0, h2);
                hrow[loc + 2] = pkh(h1, h3);
            }
        }
        HBAR(hf + 1);   // publish h(it) within this 4-warp half
    }

    // ---- tail: GEMM2(7) ----
    {
        const uint32_t* hb = hbuf1;
        const uint4* pb = sW2h + ((e1 * 4 + 3) * 8 + wm * 2) * 128 + lane;
        uint4 a0c = __ldg(pb), a1c = __ldg(pb + 128);
        #pragma unroll
        for (int ks = 0; ks < 4; ks++) {
            uint4 a0n, a1n;
            if (ks < 3) { a0n = __ldg(pb + (ks + 1) * 32); a1n = __ldg(pb + 128 + (ks + 1) * 32); }
            const uint32_t* hr0 = hb + (8 * ks + t) * SHW;
            const uint32_t* hr1 = hr0 + 4 * SHW;
            uint2 q00 = *(const uint2*)(hr0 + 2 * g);
            uint2 q10 = *(const uint2*)(hr1 + 2 * g);
            uint2 q01 = *(const uint2*)(hr0 + 16 + 2 * g);
            uint2 q11 = *(const uint2*)(hr1 + 16 + 2 * g);
            mmah(acc2[0][0], a0c, q00.x, q10.x);
            mmah(acc2[0][1], a0c, q00.y, q10.y);
            mmah(acc2[0][2], a0c, q01.x, q11.x);
            mmah(acc2[0][3], a0c, q01.y, q11.y);
            mmah(acc2[1][0], a1c, q00.x, q10.x);
            mmah(acc2[1][1], a1c, q00.y, q10.y);
            mmah(acc2[1][2], a1c, q01.x, q11.x);
            mmah(acc2[1][3], a1c, q01.y, q11.y);
            a0c = a0n; a1c = a1n;
        }
    }

    // ---- final store: acc2 + gated b2 -> out ----
    {
        float* ob = out + (size_t)b * COUT * HW + p0 + hf * 32;
        #pragma unroll
        for (int mi = 0; mi < 2; mi++) {
            int oc = wm * 32 + 16 * mi + g;
            float gba = smf[OGB + oc], gbb = smf[OGB + oc + 8];
            #pragma unroll
            for (int ni = 0; ni < 4; ni++) {
                int px = 8 * ni + 2 * t;
                *(float2*)(ob + (size_t)oc * HW + px) =
                    make_float2(acc2[mi][ni][0] + gba, acc2[mi][ni][1] + gba);
                *(float2*)(ob + (size_t)(oc + 8) * HW + px) =
                    make_float2(acc2[mi][ni][2] + gbb, acc2[mi][ni][3] + gbb);
            }
        }
    }
}

extern "C" void kernel_launch(void* const* d_in, const int* in_sizes, int n_in,
                              void* d_out, int out_size) {
    const float* x   = (const float*)d_in[0];
    const float* wts = (const float*)d_in[1];
    const int*   idx = (const int*)d_in[2];
    const float* W1  = (const float*)d_in[3];
    const float* b1  = (const float*)d_in[4];
    const float* W2  = (const float*)d_in[5];
    const float* b2  = (const float*)d_in[6];
    float* out = (float*)d_out;
    (void)in_sizes; (void)n_in; (void)out_size;

    prep_idx<<<1, 256>>>(idx);
    prep_wh<<<64, 512>>>(W1, W2);

    cudaFuncSetAttribute(moe_fp16, cudaFuncAttributeMaxDynamicSharedMemorySize, SMB);
    dim3 grid(NTILE, 128);
    moe_fp16<<<grid, NT, SMB>>>(x, wts, b1, b2, out);
}